// round 11
// baseline (speedup 1.0000x reference)
#include <cuda_runtime.h>
#include <cuda_bf16.h>
#include <cstdint>
#include <math.h>

// Problem shapes (fixed by dataset)
#define BB 2
#define NN 512
#define MM 512
#define DD 256
#define KF 640            // heads * 10 symmetric features
#define RTOT 1024         // BB*NN projection rows

// bf16 scratch (elements)
#define O_FV 0            // vision features  [RTOT][KF]
#define O_FT 655360       // text features    [RTOT][KF]
#define O_E  1310720      // exp scores       [BB][NN][MM]
#define O_ET 1835008      // exp scores^T     [BB][MM][NN]
#define BF_TOTAL 2359296

__device__ __align__(16) __nv_bfloat16 g_bf[BF_TOTAL];
__device__ float g_rs[RTOT];

__device__ __forceinline__ void cp16(uint32_t dst, const void* src) {
    asm volatile("cp.async.ca.shared.global [%0], [%1], 16;\n" :: "r"(dst), "l"(src));
}
__device__ __forceinline__ void cp_commit() {
    asm volatile("cp.async.commit_group;\n");
}
template <int N> __device__ __forceinline__ void cp_wait() {
    asm volatile("cp.async.wait_group %0;\n" :: "n"(N));
}
__device__ __forceinline__ unsigned pack_bf2(float x, float y) {
    __nv_bfloat162 h = __floats2bfloat162_rn(x, y);
    return *reinterpret_cast<unsigned*>(&h);
}
// volatile + "memory" are load-bearing (R9 failure: hoist/CSE across sync).
__device__ __forceinline__ void ldsm_x4(unsigned r[4], uint32_t addr) {
    asm volatile("ldmatrix.sync.aligned.m8n8.x4.shared.b16 {%0,%1,%2,%3}, [%4];"
        : "=r"(r[0]), "=r"(r[1]), "=r"(r[2]), "=r"(r[3]) : "r"(addr) : "memory");
}
__device__ __forceinline__ void ldsm_x2(unsigned r[2], uint32_t addr) {
    asm volatile("ldmatrix.sync.aligned.m8n8.x2.shared.b16 {%0,%1}, [%2];"
        : "=r"(r[0]), "=r"(r[1]) : "r"(addr) : "memory");
}

// =============================== PROJ (tf32) ================================
// Raw fp32 inputs via cp.async (hardware truncates to tf32 in the MMA).
// 64x64 tile, 512 thr = 4 split-K groups x (2x2 warps). K=256 -> 2 supers.
#define PTILEF 2304                 // fp32 words per tile (64*36)
#define PSLABF (2*PTILEF)
#define DSMEM_PROJ (8*PSLABF*4)     // 147456

__global__ void __launch_bounds__(512)
proj_k(const float* __restrict__ vis, const float* __restrict__ txt,
       const float* __restrict__ Wv, const float* __restrict__ Wt,
       const float* __restrict__ bv, const float* __restrict__ bt)
{
    extern __shared__ __align__(16) float dsmf[];
    const int z = blockIdx.z;
    const int linear = blockIdx.x + blockIdx.y * gridDim.x +
                       z * gridDim.x * gridDim.y;
    if (linear < 2) g_rs[linear * 512 + threadIdx.x] = 0.0f;

    const float* A   = z ? txt : vis;
    const float* W   = z ? Wt : Wv;
    const float* bia = z ? bt : bv;
    __nv_bfloat16* Fout = g_bf + (z ? O_FT : O_FV);
    const float fmult = z ? 2.0f : 1.0f;

    const int rowBase = blockIdx.y * 64;
    const int colBase = blockIdx.x * 64;
    const int tid = threadIdx.x;
    const int lane = tid & 31, wid = tid >> 5;
    const int group = wid >> 2;
    const int wm = (wid >> 1) & 1, wn = wid & 1, g = lane >> 2, q = lane & 3;

    float acc[2][4][4];
#pragma unroll
    for (int mt = 0; mt < 2; mt++)
#pragma unroll
        for (int nt = 0; nt < 4; nt++)
#pragma unroll
            for (int r = 0; r < 4; r++) acc[mt][nt][r] = 0.0f;

    const uint32_t smbase = (uint32_t)__cvta_generic_to_shared(dsmf);
    auto fillSlab = [&](int slot, int k0) {
        int r = tid >> 3, ch = tid & 7;
        cp16(smbase + (uint32_t)slot * PSLABF * 4 + (r * 36 + ch * 4) * 4,
             A + (long)(rowBase + r) * DD + k0 + ch * 4);
        cp16(smbase + ((uint32_t)slot * PSLABF + PTILEF) * 4 + (r * 36 + ch * 4) * 4,
             W + (long)(colBase + r) * DD + k0 + ch * 4);
    };
    auto fillSuper = [&](int js) {
        int slot0 = (js & 1) * 4;
#pragma unroll
        for (int s = 0; s < 4; s++) fillSlab(slot0 + s, js * 128 + s * 32);
    };

    const int r0a = wm * 32, c0b = wn * 32;
    fillSuper(0); cp_commit();
    fillSuper(1); cp_commit();

#pragma unroll
    for (int j = 0; j < 2; j++) {
        cp_wait<1>();
        __syncthreads();
        const int slab = (j & 1) * 4 + group;
        const unsigned* fA = (const unsigned*)(dsmf + (long)slab * PSLABF);
        const unsigned* fB = fA + PTILEF;
#pragma unroll
        for (int ks = 0; ks < 4; ks++) {
            unsigned a[2][4], b[4][2];
#pragma unroll
            for (int mt = 0; mt < 2; mt++) {
                int r0 = r0a + mt * 16;
                a[mt][0] = fA[(r0 + g)     * 36 + ks * 8 + q];
                a[mt][1] = fA[(r0 + 8 + g) * 36 + ks * 8 + q];
                a[mt][2] = fA[(r0 + g)     * 36 + ks * 8 + 4 + q];
                a[mt][3] = fA[(r0 + 8 + g) * 36 + ks * 8 + 4 + q];
            }
#pragma unroll
            for (int nt = 0; nt < 4; nt++) {
                int c0 = c0b + nt * 8;
                b[nt][0] = fB[(c0 + g) * 36 + ks * 8 + q];
                b[nt][1] = fB[(c0 + g) * 36 + ks * 8 + 4 + q];
            }
#pragma unroll
            for (int mt = 0; mt < 2; mt++)
#pragma unroll
                for (int nt = 0; nt < 4; nt++) {
                    asm("mma.sync.aligned.m16n8k8.row.col.f32.tf32.tf32.f32 "
                        "{%0,%1,%2,%3},{%4,%5,%6,%7},{%8,%9},{%0,%1,%2,%3};"
                        : "+f"(acc[mt][nt][0]), "+f"(acc[mt][nt][1]),
                          "+f"(acc[mt][nt][2]), "+f"(acc[mt][nt][3])
                        : "r"(a[mt][0]), "r"(a[mt][1]),
                          "r"(a[mt][2]), "r"(a[mt][3]),
                          "r"(b[nt][0]), "r"(b[nt][1]));
                }
        }
        __syncthreads();
        cp_commit();
    }

    // split-K reduction
    float* red = dsmf;
    if (group > 0) {
        float (*Rs)[66] = (float (*)[66])(red + (group - 1) * 4224);
#pragma unroll
        for (int mt = 0; mt < 2; mt++)
#pragma unroll
            for (int nt = 0; nt < 4; nt++) {
                int lr = wm * 32 + mt * 16 + g;
                int lc = wn * 32 + nt * 8 + 2 * q;
                Rs[lr][lc]         = acc[mt][nt][0];
                Rs[lr][lc + 1]     = acc[mt][nt][1];
                Rs[lr + 8][lc]     = acc[mt][nt][2];
                Rs[lr + 8][lc + 1] = acc[mt][nt][3];
            }
    }
    __syncthreads();
    if (group == 0) {
#pragma unroll
        for (int r = 0; r < 3; r++) {
            const float (*Rs)[66] = (const float (*)[66])(red + r * 4224);
#pragma unroll
            for (int mt = 0; mt < 2; mt++)
#pragma unroll
                for (int nt = 0; nt < 4; nt++) {
                    int lr = wm * 32 + mt * 16 + g;
                    int lc = wn * 32 + nt * 8 + 2 * q;
                    acc[mt][nt][0] += Rs[lr][lc];
                    acc[mt][nt][1] += Rs[lr][lc + 1];
                    acc[mt][nt][2] += Rs[lr + 8][lc];
                    acc[mt][nt][3] += Rs[lr + 8][lc + 1];
                }
        }
    }
    __syncthreads();

    // stage + quat-normalize + 10-feature expansion -> bf16
    float (*Cs)[65] = (float (*)[65])dsmf;
    if (group == 0) {
#pragma unroll
        for (int mt = 0; mt < 2; mt++)
#pragma unroll
            for (int nt = 0; nt < 4; nt++) {
                int lr = wm * 32 + mt * 16 + g;
                int lc = wn * 32 + nt * 8 + 2 * q;
                Cs[lr][lc]         = acc[mt][nt][0];
                Cs[lr][lc + 1]     = acc[mt][nt][1];
                Cs[lr + 8][lc]     = acc[mt][nt][2];
                Cs[lr + 8][lc + 1] = acc[mt][nt][3];
            }
    }
    __syncthreads();
#pragma unroll
    for (int c = 0; c < 2; c++) {
        int qi = tid + 512 * c;
        int lr = qi >> 4;
        int hq = qi & 15;
        float4 bb = *(const float4*)(bia + colBase + hq * 4);
        float w  = Cs[lr][hq * 4 + 0] + bb.x;
        float x  = Cs[lr][hq * 4 + 1] + bb.y;
        float y  = Cs[lr][hq * 4 + 2] + bb.z;
        float zz = Cs[lr][hq * 4 + 3] + bb.w;
        float inv = 1.0f / (sqrtf(w * w + x * x + y * y + zz * zz) + 1e-8f);
        w *= inv; x *= inv; y *= inv; zz *= inv;
        unsigned* o = (unsigned*)(Fout + (long)(rowBase + lr) * KF +
                                  ((colBase >> 2) + hq) * 10);
        o[0] = pack_bf2(w * w,          fmult * w * x);
        o[1] = pack_bf2(fmult * w * y,  fmult * w * zz);
        o[2] = pack_bf2(x * x,          fmult * x * y);
        o[3] = pack_bf2(fmult * x * zz, y * y);
        o[4] = pack_bf2(fmult * y * zz, zz * zz);
    }
}

// =============================== SCORE (bf16) ===============================
#define PITCHW 20               // words per smem tile row (80 B)
#define TILEW (64*PITCHW)
#define SLABW (2*TILEW)
#define DSMEM_SCORE (8*SLABW*4) // 81920

__device__ __forceinline__ void gemm_bf16(
    const __nv_bfloat16* __restrict__ A, const __nv_bfloat16* __restrict__ B,
    int Kdim, int lda, int ldb, int rowBase, int colBase,
    unsigned* dsm, float acc[2][4][4])
{
    const int tid   = threadIdx.x;
    const int lane  = tid & 31;
    const int wid   = tid >> 5;
    const int group = wid >> 2;
    const int wm    = (wid >> 1) & 1;
    const int wn    = wid & 1;
    const int g     = lane >> 2;
    const int q     = lane & 3;

#pragma unroll
    for (int mt = 0; mt < 2; mt++)
#pragma unroll
        for (int nt = 0; nt < 4; nt++)
#pragma unroll
            for (int r = 0; r < 4; r++) acc[mt][nt][r] = 0.0f;

    const uint32_t smbase = (uint32_t)__cvta_generic_to_shared(dsm);
    auto fillSlab = [&](int slot, int k0) {
        const int sel = tid >> 8;
        const int r   = (tid & 255) >> 2;
        const int ch  = tid & 3;
        const __nv_bfloat16* src = sel ? B + (long)(colBase + r) * ldb
                                       : A + (long)(rowBase + r) * lda;
        cp16(smbase + (slot * SLABW + sel * TILEW) * 4 + r * 80 + ch * 16,
             src + k0 + ch * 8);
    };
    auto fillSuper = [&](int js) {
        const int slot0 = (js & 1) * 4;
#pragma unroll
        for (int s = 0; s < 4; s++) fillSlab(slot0 + s, js * 128 + s * 32);
    };

    const int r0a = wm * 32, c0b = wn * 32;
    const int nSuper = Kdim >> 7;
    const int lane7 = lane & 7;
    const uint32_t aOff = smbase +
        (uint32_t)((r0a + ((lane >> 3) & 1) * 8 + lane7) * 80 + (lane >> 4) * 16);
    const uint32_t bOff = smbase + TILEW * 4 +
        (uint32_t)((c0b + lane7) * 80 + ((lane >> 3) & 1) * 16);

    fillSuper(0); cp_commit();
    if (nSuper > 1) fillSuper(1);
    cp_commit();

    for (int j = 0; j < nSuper; j++) {
        cp_wait<1>();
        __syncthreads();
        const int slab = (j & 1) * 4 + group;
        const uint32_t sb = (uint32_t)slab * SLABW * 4;
#pragma unroll
        for (int s = 0; s < 2; s++) {
            unsigned a[2][4], b[4][2];
#pragma unroll
            for (int mt = 0; mt < 2; mt++)
                ldsm_x4(a[mt], aOff + sb + mt * 1280 + s * 32);
#pragma unroll
            for (int nt = 0; nt < 4; nt++)
                ldsm_x2(b[nt], bOff + sb + nt * 640 + s * 32);
#pragma unroll
            for (int mt = 0; mt < 2; mt++)
#pragma unroll
                for (int nt = 0; nt < 4; nt++) {
                    asm("mma.sync.aligned.m16n8k16.row.col.f32.bf16.bf16.f32 "
                        "{%0,%1,%2,%3},{%4,%5,%6,%7},{%8,%9},{%0,%1,%2,%3};"
                        : "+f"(acc[mt][nt][0]), "+f"(acc[mt][nt][1]),
                          "+f"(acc[mt][nt][2]), "+f"(acc[mt][nt][3])
                        : "r"(a[mt][0]), "r"(a[mt][1]),
                          "r"(a[mt][2]), "r"(a[mt][3]),
                          "r"(b[nt][0]), "r"(b[nt][1]));
                }
        }
        __syncthreads();
        if (j + 2 < nSuper) fillSuper(j + 2);
        cp_commit();
    }

    float* red = (float*)dsm;
    if (group > 0) {
        float (*Rs)[66] = (float (*)[66])(red + (group - 1) * 4224);
#pragma unroll
        for (int mt = 0; mt < 2; mt++)
#pragma unroll
            for (int nt = 0; nt < 4; nt++) {
                int lr = wm * 32 + mt * 16 + g;
                int lc = wn * 32 + nt * 8 + 2 * q;
                Rs[lr][lc]         = acc[mt][nt][0];
                Rs[lr][lc + 1]     = acc[mt][nt][1];
                Rs[lr + 8][lc]     = acc[mt][nt][2];
                Rs[lr + 8][lc + 1] = acc[mt][nt][3];
            }
    }
    __syncthreads();
    if (group == 0) {
#pragma unroll
        for (int r = 0; r < 3; r++) {
            const float (*Rs)[66] = (const float (*)[66])(red + r * 4224);
#pragma unroll
            for (int mt = 0; mt < 2; mt++)
#pragma unroll
                for (int nt = 0; nt < 4; nt++) {
                    int lr = wm * 32 + mt * 16 + g;
                    int lc = wn * 32 + nt * 8 + 2 * q;
                    acc[mt][nt][0] += Rs[lr][lc];
                    acc[mt][nt][1] += Rs[lr][lc + 1];
                    acc[mt][nt][2] += Rs[lr + 8][lc];
                    acc[mt][nt][3] += Rs[lr + 8][lc + 1];
                }
        }
    }
    __syncthreads();
}

__global__ void __launch_bounds__(512)
score_k()
{
    extern __shared__ __align__(16) unsigned dsm[];
    const int z = blockIdx.z;
    const __nv_bfloat16* A = g_bf + O_FV + (long)z * NN * KF;
    const __nv_bfloat16* B = g_bf + O_FT + (long)z * MM * KF;
    __nv_bfloat16* E  = g_bf + O_E  + (long)z * NN * MM;
    __nv_bfloat16* ET = g_bf + O_ET + (long)z * MM * NN;

    const int rowBase = blockIdx.y * 64;
    const int colBase = blockIdx.x * 64;
    const int tid = threadIdx.x;
    const int lane = tid & 31, wid = tid >> 5;
    const int group = wid >> 2;
    const int wm = (wid >> 1) & 1, wn = wid & 1, g = lane >> 2, q = lane & 3;

    float acc[2][4][4];
    gemm_bf16(A, B, KF, KF, KF, rowBase, colBase, dsm, acc);

    float (*Cs)[65] = (float (*)[65])dsm;
    if (group == 0) {
        const float SC = 1.0f / 1024.0f;
        float rsum[2][2] = {{0.f, 0.f}, {0.f, 0.f}};
#pragma unroll
        for (int mt = 0; mt < 2; mt++)
#pragma unroll
            for (int nt = 0; nt < 4; nt++) {
                int lr = wm * 32 + mt * 16 + g;
                int lc = wn * 32 + nt * 8 + 2 * q;
                float e0 = __expf(acc[mt][nt][0] * SC);
                float e1 = __expf(acc[mt][nt][1] * SC);
                float e2 = __expf(acc[mt][nt][2] * SC);
                float e3 = __expf(acc[mt][nt][3] * SC);
                Cs[lr][lc]         = e0;
                Cs[lr][lc + 1]     = e1;
                Cs[lr + 8][lc]     = e2;
                Cs[lr + 8][lc + 1] = e3;
                rsum[mt][0] += e0 + e1;
                rsum[mt][1] += e2 + e3;
            }
#pragma unroll
        for (int mt = 0; mt < 2; mt++)
#pragma unroll
            for (int hh = 0; hh < 2; hh++) {
                float v = rsum[mt][hh];
                v += __shfl_xor_sync(0xffffffffu, v, 1);
                v += __shfl_xor_sync(0xffffffffu, v, 2);
                if (q == 0) {
                    int row = rowBase + wm * 32 + mt * 16 + hh * 8 + g;
                    atomicAdd(&g_rs[z * NN + row], v);
                }
            }
    }
    __syncthreads();
    {
        int r  = tid >> 3;
        int c0 = (tid & 7) * 8;
        uint4 o = make_uint4(pack_bf2(Cs[r][c0],     Cs[r][c0 + 1]),
                             pack_bf2(Cs[r][c0 + 2], Cs[r][c0 + 3]),
                             pack_bf2(Cs[r][c0 + 4], Cs[r][c0 + 5]),
                             pack_bf2(Cs[r][c0 + 6], Cs[r][c0 + 7]));
        *(uint4*)(E + (long)(rowBase + r) * MM + colBase + c0) = o;
    }
    {
        int c  = tid >> 3;
        int r0 = (tid & 7) * 8;
        uint4 o = make_uint4(pack_bf2(Cs[r0][c],     Cs[r0 + 1][c]),
                             pack_bf2(Cs[r0 + 2][c], Cs[r0 + 3][c]),
                             pack_bf2(Cs[r0 + 4][c], Cs[r0 + 5][c]),
                             pack_bf2(Cs[r0 + 6][c], Cs[r0 + 7][c]));
        *(uint4*)(ET + (long)(colBase + c) * NN + rowBase + r0) = o;
    }
}

// ================================ OUT (bf16) ================================
// B operand built resident in smem from fp32 (scale+convert+transpose fused):
//   sel=0: B_s[d][m] = bf16(text[b][m][colBase+d])           A = E   (k=m)
//   sel=1: B_s[d][n] = bf16(vision[b][n][colBase+d]/rs[n])   A = E^T (k=n)
#define A_SLABB 5120                    // 64 rows * 80 B
#define BS_OFF  (8*A_SLABB)             // 40960
#define PB 1040                         // B_s row pitch bytes (512 bf16 + pad)
#define DSMEM_OUT (BS_OFF + 64*PB)      // 107520

__global__ void __launch_bounds__(512)
out_k(const float* __restrict__ vis, const float* __restrict__ txt,
      const float* __restrict__ hptr, float* __restrict__ outv,
      float* __restrict__ outt)
{
    extern __shared__ __align__(16) unsigned dsm[];
    const int zz = blockIdx.z;
    const int b = zz & 1;
    const int sel = zz >> 1;

    const int rowBase = blockIdx.y * 64;
    const int colBase = blockIdx.x * 64;
    const int tid = threadIdx.x;
    const int lane = tid & 31, wid = tid >> 5;
    const int group = wid >> 2;
    const int wm = (wid >> 1) & 1, wn = wid & 1, g = lane >> 2, q = lane & 3;
    const int r0a = wm * 32, c0b = wn * 32;

    const __nv_bfloat16* A = sel ? g_bf + O_ET + (long)b * MM * NN
                                 : g_bf + O_E  + (long)b * NN * MM;
    const float* srcB = sel ? vis + (long)b * NN * DD
                            : txt + (long)b * MM * DD;

    float acc[2][4][4];
#pragma unroll
    for (int mt = 0; mt < 2; mt++)
#pragma unroll
        for (int nt = 0; nt < 4; nt++)
#pragma unroll
            for (int r = 0; r < 4; r++) acc[mt][nt][r] = 0.0f;

    const uint32_t smbase = (uint32_t)__cvta_generic_to_shared(dsm);
    auto fillSuper = [&](int js) {
        const int slot0 = (js & 1) * 4;
#pragma unroll
        for (int p = 0; p < 2; p++) {
            int cid = tid + p * 512;
            int sl = cid >> 8, w = cid & 255;
            int r = w >> 2, ch = w & 3;
            cp16(smbase + (slot0 + sl) * A_SLABB + r * 80 + ch * 16,
                 A + (long)(rowBase + r) * 512 + js * 128 + sl * 32 + ch * 8);
        }
    };

    fillSuper(0); cp_commit();
    fillSuper(1); cp_commit();

    // Build resident B_s (overlaps the async A fills above)
    {
        char* dsc = (char*)dsm;
        const int rsbase = b * NN;
#pragma unroll 4
        for (int p = 0; p < 32; p++) {
            int idx = tid + p * 512;
            int k2 = idx >> 6, d = idx & 63;
            int k = k2 * 2;
            float s0 = 1.0f, s1 = 1.0f;
            if (sel) { s0 = 1.0f / g_rs[rsbase + k]; s1 = 1.0f / g_rs[rsbase + k + 1]; }
            float v0 = srcB[(long)k * DD + colBase + d];
            float v1 = srcB[(long)(k + 1) * DD + colBase + d];
            *(unsigned*)(dsc + BS_OFF + d * PB + k2 * 4) = pack_bf2(v0 * s0, v1 * s1);
        }
    }

    const int lane7 = lane & 7;
    const uint32_t aOff = smbase +
        (uint32_t)((r0a + ((lane >> 3) & 1) * 8 + lane7) * 80 + (lane >> 4) * 16);
    const uint32_t bBase = smbase + BS_OFF +
        (uint32_t)((c0b + lane7) * PB + ((lane >> 3) & 1) * 16);

#pragma unroll 1
    for (int j = 0; j < 4; j++) {
        cp_wait<1>();
        __syncthreads();          // also covers B_s build on iteration 0
        const int slab = (j & 1) * 4 + group;
        const uint32_t sa = aOff + slab * A_SLABB;
        const int kg = j * 128 + group * 32;
#pragma unroll
        for (int s = 0; s < 2; s++) {
            unsigned a[2][4], bb[4][2];
            ldsm_x4(a[0], sa + s * 32);
            ldsm_x4(a[1], sa + 1280 + s * 32);
#pragma unroll
            for (int nt = 0; nt < 4; nt++)
                ldsm_x2(bb[nt], bBase + nt * 8 * PB + (kg + s * 16) * 2);
#pragma unroll
            for (int mt = 0; mt < 2; mt++)
#pragma unroll
                for (int nt = 0; nt < 4; nt++) {
                    asm("mma.sync.aligned.m16n8k16.row.col.f32.bf16.bf16.f32 "
                        "{%0,%1,%2,%3},{%4,%5,%6,%7},{%8,%9},{%0,%1,%2,%3};"
                        : "+f"(acc[mt][nt][0]), "+f"(acc[mt][nt][1]),
                          "+f"(acc[mt][nt][2]), "+f"(acc[mt][nt][3])
                        : "r"(a[mt][0]), "r"(a[mt][1]),
                          "r"(a[mt][2]), "r"(a[mt][3]),
                          "r"(bb[nt][0]), "r"(bb[nt][1]));
                }
        }
        __syncthreads();
        if (j + 2 < 4) fillSuper(j + 2);
        cp_commit();
    }

    // split-K reduction (A ring + B_s both dead now)
    float* red = (float*)dsm;
    if (group > 0) {
        float (*Rs)[66] = (float (*)[66])(red + (group - 1) * 4224);
#pragma unroll
        for (int mt = 0; mt < 2; mt++)
#pragma unroll
            for (int nt = 0; nt < 4; nt++) {
                int lr = wm * 32 + mt * 16 + g;
                int lc = wn * 32 + nt * 8 + 2 * q;
                Rs[lr][lc]         = acc[mt][nt][0];
                Rs[lr][lc + 1]     = acc[mt][nt][1];
                Rs[lr + 8][lc]     = acc[mt][nt][2];
                Rs[lr + 8][lc + 1] = acc[mt][nt][3];
            }
    }
    __syncthreads();
    if (group == 0) {
#pragma unroll
        for (int r = 0; r < 3; r++) {
            const float (*Rs)[66] = (const float (*)[66])(red + r * 4224);
#pragma unroll
            for (int mt = 0; mt < 2; mt++)
#pragma unroll
                for (int nt = 0; nt < 4; nt++) {
                    int lr = wm * 32 + mt * 16 + g;
                    int lc = wn * 32 + nt * 8 + 2 * q;
                    acc[mt][nt][0] += Rs[lr][lc];
                    acc[mt][nt][1] += Rs[lr][lc + 1];
                    acc[mt][nt][2] += Rs[lr + 8][lc];
                    acc[mt][nt][3] += Rs[lr + 8][lc + 1];
                }
        }

        const float h = __ldg(hptr);
        if (sel == 0) {
            const float* base = vis + (long)b * NN * DD;
            float* C = outv + (long)b * NN * DD;
#pragma unroll
            for (int mt = 0; mt < 2; mt++) {
                int r0 = rowBase + wm * 32 + mt * 16 + g;
                float s0 = h / g_rs[b * NN + r0];
                float s1 = h / g_rs[b * NN + r0 + 8];
#pragma unroll
                for (int nt = 0; nt < 4; nt++) {
                    int col = colBase + wn * 32 + nt * 8 + 2 * q;
                    float2 b0 = *(const float2*)(base + (long)r0 * DD + col);
                    float2 b1 = *(const float2*)(base + (long)(r0 + 8) * DD + col);
                    *(float2*)(C + (long)r0 * DD + col) =
                        make_float2(b0.x + s0 * acc[mt][nt][0], b0.y + s0 * acc[mt][nt][1]);
                    *(float2*)(C + (long)(r0 + 8) * DD + col) =
                        make_float2(b1.x + s1 * acc[mt][nt][2], b1.y + s1 * acc[mt][nt][3]);
                }
            }
        } else {
            const float* base = txt + (long)b * MM * DD;
            float* C = outt + (long)b * MM * DD;
#pragma unroll
            for (int mt = 0; mt < 2; mt++) {
                int r0 = rowBase + wm * 32 + mt * 16 + g;
#pragma unroll
                for (int nt = 0; nt < 4; nt++) {
                    int col = colBase + wn * 32 + nt * 8 + 2 * q;
                    float2 b0 = *(const float2*)(base + (long)r0 * DD + col);
                    float2 b1 = *(const float2*)(base + (long)(r0 + 8) * DD + col);
                    *(float2*)(C + (long)r0 * DD + col) =
                        make_float2(b0.x + h * acc[mt][nt][0], b0.y + h * acc[mt][nt][1]);
                    *(float2*)(C + (long)(r0 + 8) * DD + col) =
                        make_float2(b1.x + h * acc[mt][nt][2], b1.y + h * acc[mt][nt][3]);
                }
            }
        }
    }
}

// ---------------------------------------------------------------------------
extern "C" void kernel_launch(void* const* d_in, const int* in_sizes, int n_in,
                              void* d_out, int out_size)
{
    (void)in_sizes; (void)n_in; (void)out_size;

    const float* vision = (const float*)d_in[0];
    const float* text   = (const float*)d_in[1];
    const float* Wv     = (const float*)d_in[2];
    const float* bv     = (const float*)d_in[3];
    const float* Wt     = (const float*)d_in[4];
    const float* bt     = (const float*)d_in[5];
    const float* hp     = (const float*)d_in[6];

    float* outv = (float*)d_out;
    float* outt = outv + (size_t)BB * NN * DD;

    cudaFuncSetAttribute(proj_k,  cudaFuncAttributeMaxDynamicSharedMemorySize, DSMEM_PROJ);
    cudaFuncSetAttribute(score_k, cudaFuncAttributeMaxDynamicSharedMemorySize, DSMEM_SCORE);
    cudaFuncSetAttribute(out_k,   cudaFuncAttributeMaxDynamicSharedMemorySize, DSMEM_OUT);

    // 1) Projections (tf32 on raw fp32) + quat features + rowsum zero
    proj_k<<<dim3(DD / 64, RTOT / 64, 2), 512, DSMEM_PROJ>>>(
        vision, text, Wv, Wt, bv, bt);
    // 2) Score GEMM + exp + E/E^T + rowsums
    score_k<<<dim3(MM / 64, NN / 64, BB), 512, DSMEM_SCORE>>>();
    // 3) Both outputs; B operand built resident in smem (fuses transpose+scale)
    out_k<<<dim3(DD / 64, NN / 64, 4), 512, DSMEM_OUT>>>(
        vision, text, hp, outv, outt);
}

// round 12
// speedup vs baseline: 1.2695x; 1.2695x over previous
#include <cuda_runtime.h>
#include <cuda_bf16.h>
#include <cstdint>
#include <math.h>

// Problem shapes (fixed by dataset)
#define BB 2
#define NN 512
#define MM 512
#define DD 256
#define KF 640            // heads * 10 symmetric features
#define RTOT 1024         // BB*NN projection rows

// bf16 scratch offsets (elements); all divisible by 8 -> 16B aligned
#define O_VB  0           // vision bf16            [RTOT][DD]
#define O_TB  262144      // text bf16              [RTOT][DD]
#define O_WVB 524288      // Wv bf16                [DD][DD]
#define O_WTB 589824      // Wt bf16                [DD][DD]
#define O_TBT 655360      // text^T bf16            [BB][DD][MM]
#define O_FV  917504      // vision features        [RTOT][KF]
#define O_FT  1572864     // text features          [RTOT][KF]
#define O_E   2228224     // exp scores             [BB][NN][MM]
#define O_ET  2752512     // exp scores transposed  [BB][MM][NN]
#define O_VST 3276800     // (vision/rowsum)^T      [BB][DD][NN]
#define BF_TOTAL 3538944

__device__ __align__(16) __nv_bfloat16 g_bf[BF_TOTAL];
__device__ float g_rs[RTOT];

__device__ __forceinline__ void cp16(uint32_t dst, const void* src) {
    asm volatile("cp.async.ca.shared.global [%0], [%1], 16;\n" :: "r"(dst), "l"(src));
}
__device__ __forceinline__ void cp_commit() {
    asm volatile("cp.async.commit_group;\n");
}
template <int N> __device__ __forceinline__ void cp_wait() {
    asm volatile("cp.async.wait_group %0;\n" :: "n"(N));
}
__device__ __forceinline__ unsigned pack_bf2(float x, float y) {
    __nv_bfloat162 h = __floats2bfloat162_rn(x, y);
    return *reinterpret_cast<unsigned*>(&h);
}
// volatile + "memory" are load-bearing (R9 failure: hoist/CSE across sync).
__device__ __forceinline__ void ldsm_x4(unsigned r[4], uint32_t addr) {
    asm volatile("ldmatrix.sync.aligned.m8n8.x4.shared.b16 {%0,%1,%2,%3}, [%4];"
        : "=r"(r[0]), "=r"(r[1]), "=r"(r[2]), "=r"(r[3]) : "r"(addr) : "memory");
}
__device__ __forceinline__ void ldsm_x2(unsigned r[2], uint32_t addr) {
    asm volatile("ldmatrix.sync.aligned.m8n8.x2.shared.b16 {%0,%1}, [%2];"
        : "=r"(r[0]), "=r"(r[1]) : "r"(addr) : "memory");
}

#define PITCHW 20               // 32-bit words per smem tile row (= 80 bytes)
#define TILEW (64*PITCHW)       // words per operand tile (64 rows)
#define SLABW (2*TILEW)         // A+B tile per 32-k slab
#define DSMEM_BYTES (8*SLABW*4) // 2 supers x 4 slabs = 81920 B

// ---------------------------------------------------------------------------
// bf16 m16n8k16 MMA mainloop, 4-way warp-group split-K, ldmatrix frag loads.
// C tile 64x64, 512 threads = 4 groups x (2x2 warps, 32x32/warp).
// Super-iteration = 128 of K (4 slabs of 32); group g computes slab g.
// Both operands k-contiguous in gmem: X(i,k) = X[i*ld + k].
// After the loop group 0 owns the reduced fp32 accumulators.
// ---------------------------------------------------------------------------
__device__ __forceinline__ void gemm_bf16(
    const __nv_bfloat16* __restrict__ A, const __nv_bfloat16* __restrict__ B,
    int Kdim, int lda, int ldb, int rowBase, int colBase,
    unsigned* dsm, float acc[2][4][4])
{
    const int tid   = threadIdx.x;
    const int lane  = tid & 31;
    const int wid   = tid >> 5;
    const int group = wid >> 2;
    const int wm    = (wid >> 1) & 1;
    const int wn    = wid & 1;
    const int g     = lane >> 2;
    const int q     = lane & 3;

#pragma unroll
    for (int mt = 0; mt < 2; mt++)
#pragma unroll
        for (int nt = 0; nt < 4; nt++)
#pragma unroll
            for (int r = 0; r < 4; r++) acc[mt][nt][r] = 0.0f;

    const uint32_t smbase = (uint32_t)__cvta_generic_to_shared(dsm);

    // One cp16 per thread per slab: 512 threads cover A(256 chunks)+B(256).
    auto fillSlab = [&](int slot, int k0) {
        const int sel = tid >> 8;          // 0 = A, 1 = B
        const int r   = (tid & 255) >> 2;  // tile row 0..63
        const int ch  = tid & 3;           // 16B chunk (8 bf16)
        const __nv_bfloat16* src = sel ? B + (long)(colBase + r) * ldb
                                       : A + (long)(rowBase + r) * lda;
        cp16(smbase + (slot * SLABW + sel * TILEW) * 4 + r * 80 + ch * 16,
             src + k0 + ch * 8);
    };
    auto fillSuper = [&](int js) {
        const int slot0 = (js & 1) * 4;
#pragma unroll
        for (int s = 0; s < 4; s++) fillSlab(slot0 + s, js * 128 + s * 32);
    };

    const int r0a = wm * 32, c0b = wn * 32;
    const int nSuper = Kdim >> 7;

    // ldmatrix lane-address bases (bytes, shared address space)
    const int lane7 = lane & 7;
    const uint32_t aOff = smbase +
        (uint32_t)((r0a + ((lane >> 3) & 1) * 8 + lane7) * 80 + (lane >> 4) * 16);
    const uint32_t bOff = smbase + TILEW * 4 +
        (uint32_t)((c0b + lane7) * 80 + ((lane >> 3) & 1) * 16);

    fillSuper(0); cp_commit();
    if (nSuper > 1) fillSuper(1);
    cp_commit();

    for (int j = 0; j < nSuper; j++) {
        cp_wait<1>();
        __syncthreads();

        const int slab = (j & 1) * 4 + group;
        const uint32_t sb = (uint32_t)slab * SLABW * 4;

#pragma unroll
        for (int s = 0; s < 2; s++) {
            unsigned a[2][4], b[4][2];
#pragma unroll
            for (int mt = 0; mt < 2; mt++)
                ldsm_x4(a[mt], aOff + sb + mt * 1280 + s * 32);
#pragma unroll
            for (int nt = 0; nt < 4; nt++)
                ldsm_x2(b[nt], bOff + sb + nt * 640 + s * 32);
#pragma unroll
            for (int mt = 0; mt < 2; mt++)
#pragma unroll
                for (int nt = 0; nt < 4; nt++) {
                    asm("mma.sync.aligned.m16n8k16.row.col.f32.bf16.bf16.f32 "
                        "{%0,%1,%2,%3},{%4,%5,%6,%7},{%8,%9},{%0,%1,%2,%3};"
                        : "+f"(acc[mt][nt][0]), "+f"(acc[mt][nt][1]),
                          "+f"(acc[mt][nt][2]), "+f"(acc[mt][nt][3])
                        : "r"(a[mt][0]), "r"(a[mt][1]),
                          "r"(a[mt][2]), "r"(a[mt][3]),
                          "r"(b[nt][0]), "r"(b[nt][1]));
                }
        }

        __syncthreads();
        if (j + 2 < nSuper) fillSuper(j + 2);
        cp_commit();
    }

    // split-K reduction: groups 1..3 stage to smem, group 0 accumulates
    float* red = (float*)dsm;
    if (group > 0) {
        float (*Rs)[66] = (float (*)[66])(red + (group - 1) * 4224);
#pragma unroll
        for (int mt = 0; mt < 2; mt++)
#pragma unroll
            for (int nt = 0; nt < 4; nt++) {
                int lr = wm * 32 + mt * 16 + g;
                int lc = wn * 32 + nt * 8 + 2 * q;
                Rs[lr][lc]         = acc[mt][nt][0];
                Rs[lr][lc + 1]     = acc[mt][nt][1];
                Rs[lr + 8][lc]     = acc[mt][nt][2];
                Rs[lr + 8][lc + 1] = acc[mt][nt][3];
            }
    }
    __syncthreads();
    if (group == 0) {
#pragma unroll
        for (int r = 0; r < 3; r++) {
            const float (*Rs)[66] = (const float (*)[66])(red + r * 4224);
#pragma unroll
            for (int mt = 0; mt < 2; mt++)
#pragma unroll
                for (int nt = 0; nt < 4; nt++) {
                    int lr = wm * 32 + mt * 16 + g;
                    int lc = wn * 32 + nt * 8 + 2 * q;
                    acc[mt][nt][0] += Rs[lr][lc];
                    acc[mt][nt][1] += Rs[lr][lc + 1];
                    acc[mt][nt][2] += Rs[lr + 8][lc];
                    acc[mt][nt][3] += Rs[lr + 8][lc + 1];
                }
        }
    }
    __syncthreads();
}

// ---------------------------------------------------------------------------
// 0) prep: fp32 -> bf16 copies, text^T bf16 (64x32 tiles, 128B stores),
//    zero rowsum.
// ---------------------------------------------------------------------------
__global__ void __launch_bounds__(256)
prep_k(const float* __restrict__ vis, const float* __restrict__ txt,
       const float* __restrict__ Wv, const float* __restrict__ Wt)
{
    __shared__ float ts[64][33];
    const int bx = blockIdx.x;
    const int tid = threadIdx.x;

    if (bx < 4) g_rs[bx * 256 + tid] = 0.0f;

    if (bx < 320) {
        // flat conversion: 655360 elements, 8 per thread
        int gid = bx * 256 + tid;
        int e = gid * 8;
        const float* src; __nv_bfloat16* dst; int off;
        if (e < 262144)      { src = vis; dst = g_bf + O_VB;  off = e; }
        else if (e < 524288) { src = txt; dst = g_bf + O_TB;  off = e - 262144; }
        else if (e < 589824) { src = Wv;  dst = g_bf + O_WVB; off = e - 524288; }
        else                 { src = Wt;  dst = g_bf + O_WTB; off = e - 589824; }
        float4 v0 = *(const float4*)(src + off);
        float4 v1 = *(const float4*)(src + off + 4);
        uint4 o = make_uint4(pack_bf2(v0.x, v0.y), pack_bf2(v0.z, v0.w),
                             pack_bf2(v1.x, v1.y), pack_bf2(v1.z, v1.w));
        *(uint4*)(dst + off) = o;
    } else {
        // text^T: 64m x 32d tiles; t in [0,128)
        int t = bx - 320;
        int m0g = (t >> 3) * 64;           // global text row (b*512+m)
        int d0 = (t & 7) * 32;
#pragma unroll
        for (int half = 0; half < 2; half++) {
            int r = (tid >> 3) + half * 32;
            int c4 = (tid & 7) * 4;
            float4 v = *(const float4*)(txt + (long)(m0g + r) * DD + d0 + c4);
            ts[r][c4] = v.x; ts[r][c4 + 1] = v.y;
            ts[r][c4 + 2] = v.z; ts[r][c4 + 3] = v.w;
        }
        __syncthreads();
        int d = tid >> 3, mc = (tid & 7) * 8;
        int b = m0g >> 9, m0 = m0g & 511;
        uint4 o = make_uint4(pack_bf2(ts[mc][d],     ts[mc + 1][d]),
                             pack_bf2(ts[mc + 2][d], ts[mc + 3][d]),
                             pack_bf2(ts[mc + 4][d], ts[mc + 5][d]),
                             pack_bf2(ts[mc + 6][d], ts[mc + 7][d]));
        *(uint4*)(g_bf + O_TBT + ((long)(b * DD + d0 + d)) * MM + m0 + mc) = o;
    }
}

// ---------------------------------------------------------------------------
// 1) Projection: z=0 vision/Wv/bv (fmult 1), z=1 text/Wt/bt (fmult 2).
//    Epilogue: +bias, quat-normalize, 10-feature expansion -> bf16 features.
// ---------------------------------------------------------------------------
__global__ void __launch_bounds__(512)
proj_k(const float* __restrict__ bv, const float* __restrict__ bt)
{
    extern __shared__ __align__(16) unsigned dsm[];
    const int z = blockIdx.z;
    const __nv_bfloat16* A = g_bf + (z ? O_TB : O_VB);
    const __nv_bfloat16* W = g_bf + (z ? O_WTB : O_WVB);
    const float* bia       = z ? bt : bv;
    __nv_bfloat16* Fout    = g_bf + (z ? O_FT : O_FV);
    const float fmult      = z ? 2.0f : 1.0f;

    const int rowBase = blockIdx.y * 64;
    const int colBase = blockIdx.x * 64;
    const int tid = threadIdx.x;
    const int lane = tid & 31, wid = tid >> 5;
    const int group = wid >> 2;
    const int wm = (wid >> 1) & 1, wn = wid & 1, g = lane >> 2, q = lane & 3;

    float acc[2][4][4];
    gemm_bf16(A, W, DD, DD, DD, rowBase, colBase, dsm, acc);

    float (*Cs)[65] = (float (*)[65])dsm;
    if (group == 0) {
#pragma unroll
        for (int mt = 0; mt < 2; mt++)
#pragma unroll
            for (int nt = 0; nt < 4; nt++) {
                int lr = wm * 32 + mt * 16 + g;
                int lc = wn * 32 + nt * 8 + 2 * q;
                Cs[lr][lc]         = acc[mt][nt][0];
                Cs[lr][lc + 1]     = acc[mt][nt][1];
                Cs[lr + 8][lc]     = acc[mt][nt][2];
                Cs[lr + 8][lc + 1] = acc[mt][nt][3];
            }
    }
    __syncthreads();
#pragma unroll
    for (int c = 0; c < 2; c++) {
        int qi = tid + 512 * c;       // 1024 quats per CTA
        int lr = qi >> 4;
        int hq = qi & 15;
        float4 bb = *(const float4*)(bia + colBase + hq * 4);
        float w  = Cs[lr][hq * 4 + 0] + bb.x;
        float x  = Cs[lr][hq * 4 + 1] + bb.y;
        float y  = Cs[lr][hq * 4 + 2] + bb.z;
        float zz = Cs[lr][hq * 4 + 3] + bb.w;
        float inv = 1.0f / (sqrtf(w * w + x * x + y * y + zz * zz) + 1e-8f);
        w *= inv; x *= inv; y *= inv; zz *= inv;
        unsigned* o = (unsigned*)(Fout + (long)(rowBase + lr) * KF +
                                  ((colBase >> 2) + hq) * 10);
        o[0] = pack_bf2(w * w,          fmult * w * x);
        o[1] = pack_bf2(fmult * w * y,  fmult * w * zz);
        o[2] = pack_bf2(x * x,          fmult * x * y);
        o[3] = pack_bf2(fmult * x * zz, y * y);
        o[4] = pack_bf2(fmult * y * zz, zz * zz);
    }
}

// ---------------------------------------------------------------------------
// 2) Score GEMM + exp epilogue; writes E (bf16), E^T (bf16), rowsum atomics.
//    Logits in [0, 1/16] -> no max subtraction needed.
// ---------------------------------------------------------------------------
__global__ void __launch_bounds__(512)
score_k()
{
    extern __shared__ __align__(16) unsigned dsm[];
    const int z = blockIdx.z;
    const __nv_bfloat16* A = g_bf + O_FV + (long)z * NN * KF;
    const __nv_bfloat16* B = g_bf + O_FT + (long)z * MM * KF;
    __nv_bfloat16* E  = g_bf + O_E  + (long)z * NN * MM;
    __nv_bfloat16* ET = g_bf + O_ET + (long)z * MM * NN;

    const int rowBase = blockIdx.y * 64;
    const int colBase = blockIdx.x * 64;
    const int tid = threadIdx.x;
    const int lane = tid & 31, wid = tid >> 5;
    const int group = wid >> 2;
    const int wm = (wid >> 1) & 1, wn = wid & 1, g = lane >> 2, q = lane & 3;

    float acc[2][4][4];
    gemm_bf16(A, B, KF, KF, KF, rowBase, colBase, dsm, acc);

    float (*Cs)[65] = (float (*)[65])dsm;
    if (group == 0) {
        const float SC = 1.0f / 1024.0f;
        float rsum[2][2] = {{0.f, 0.f}, {0.f, 0.f}};
#pragma unroll
        for (int mt = 0; mt < 2; mt++)
#pragma unroll
            for (int nt = 0; nt < 4; nt++) {
                int lr = wm * 32 + mt * 16 + g;
                int lc = wn * 32 + nt * 8 + 2 * q;
                float e0 = __expf(acc[mt][nt][0] * SC);
                float e1 = __expf(acc[mt][nt][1] * SC);
                float e2 = __expf(acc[mt][nt][2] * SC);
                float e3 = __expf(acc[mt][nt][3] * SC);
                Cs[lr][lc]         = e0;
                Cs[lr][lc + 1]     = e1;
                Cs[lr + 8][lc]     = e2;
                Cs[lr + 8][lc + 1] = e3;
                rsum[mt][0] += e0 + e1;
                rsum[mt][1] += e2 + e3;
            }
#pragma unroll
        for (int mt = 0; mt < 2; mt++)
#pragma unroll
            for (int hh = 0; hh < 2; hh++) {
                float v = rsum[mt][hh];
                v += __shfl_xor_sync(0xffffffffu, v, 1);
                v += __shfl_xor_sync(0xffffffffu, v, 2);
                if (q == 0) {
                    int row = rowBase + wm * 32 + mt * 16 + hh * 8 + g;
                    atomicAdd(&g_rs[z * NN + row], v);
                }
            }
    }
    __syncthreads();
    // E (row-major) and E^T (coalesced via smem) bf16 writes, all 512 threads
    {
        int r  = tid >> 3;
        int c0 = (tid & 7) * 8;
        uint4 o = make_uint4(pack_bf2(Cs[r][c0],     Cs[r][c0 + 1]),
                             pack_bf2(Cs[r][c0 + 2], Cs[r][c0 + 3]),
                             pack_bf2(Cs[r][c0 + 4], Cs[r][c0 + 5]),
                             pack_bf2(Cs[r][c0 + 6], Cs[r][c0 + 7]));
        *(uint4*)(E + (long)(rowBase + r) * MM + colBase + c0) = o;
    }
    {
        int c  = tid >> 3;
        int r0 = (tid & 7) * 8;
        uint4 o = make_uint4(pack_bf2(Cs[r0][c],     Cs[r0 + 1][c]),
                             pack_bf2(Cs[r0 + 2][c], Cs[r0 + 3][c]),
                             pack_bf2(Cs[r0 + 4][c], Cs[r0 + 5][c]),
                             pack_bf2(Cs[r0 + 6][c], Cs[r0 + 7][c]));
        *(uint4*)(ET + (long)(colBase + c) * NN + rowBase + r0) = o;
    }
}

// ---------------------------------------------------------------------------
// 3) vscale + transpose: VST[b][d][n] = bf16( vision[b][n][d] / rowsum[b,n] )
//    16n x 32d tiles, 512 CTAs x 128 thr (latency-bound kernel: maximize
//    CTAs/SM; one float4 load + one uint2 store per thread).
// ---------------------------------------------------------------------------
__global__ void __launch_bounds__(128)
vscale_k(const float* __restrict__ vis)
{
    __shared__ float ts[16][33];
    const int bx = blockIdx.x;            // 64 n-tiles x 8 d-tiles = 512
    const int tid = threadIdx.x;
    const int n0g = (bx >> 3) * 16;       // global row (b*512+n)
    const int d0 = (bx & 7) * 32;
    {
        int r = tid >> 3, c4 = (tid & 7) * 4;
        float inv = 1.0f / g_rs[n0g + r];
        float4 v = *(const float4*)(vis + (long)(n0g + r) * DD + d0 + c4);
        ts[r][c4] = v.x * inv; ts[r][c4 + 1] = v.y * inv;
        ts[r][c4 + 2] = v.z * inv; ts[r][c4 + 3] = v.w * inv;
    }
    __syncthreads();
    int d = tid >> 2, nc = (tid & 3) * 4;
    int b = n0g >> 9, n0 = n0g & 511;
    uint2 o = make_uint2(pack_bf2(ts[nc][d],     ts[nc + 1][d]),
                         pack_bf2(ts[nc + 2][d], ts[nc + 3][d]));
    *(uint2*)(g_bf + O_VST + ((long)(b * DD + d0 + d)) * NN + n0 + nc) = o;
}

// ---------------------------------------------------------------------------
// 4) Combined output GEMM. z=(sel<<1)|b.  All operands k-contiguous bf16.
//    sel=0: outv[b] = vision + (h/rs[n]) * E[b] @ text[b]     (A=E, B=text^T)
//    sel=1: outt[b] = text   +  h        * E^T[b] @ v'[b]     (A=E^T, B=v'^T)
// ---------------------------------------------------------------------------
__global__ void __launch_bounds__(512)
out_k(const float* __restrict__ vis, const float* __restrict__ txt,
      const float* __restrict__ hptr, float* __restrict__ outv,
      float* __restrict__ outt)
{
    extern __shared__ __align__(16) unsigned dsm[];
    const int zz = blockIdx.z;
    const int b = zz & 1;
    const int sel = zz >> 1;

    const int rowBase = blockIdx.y * 64;
    const int colBase = blockIdx.x * 64;
    const int tid = threadIdx.x;
    const int lane = tid & 31, wid = tid >> 5;
    const int group = wid >> 2;
    const int wm = (wid >> 1) & 1, wn = wid & 1, g = lane >> 2, q = lane & 3;

    float acc[2][4][4];
    const float h = __ldg(hptr);

    if (sel == 0) {
        const __nv_bfloat16* A = g_bf + O_E   + (long)b * NN * MM;
        const __nv_bfloat16* B = g_bf + O_TBT + (long)b * DD * MM;
        gemm_bf16(A, B, MM, MM, MM, rowBase, colBase, dsm, acc);
        if (group == 0) {
            const float* base = vis + (long)b * NN * DD;
            float* C = outv + (long)b * NN * DD;
#pragma unroll
            for (int mt = 0; mt < 2; mt++) {
                int r0 = rowBase + wm * 32 + mt * 16 + g;
                float s0 = h / g_rs[b * NN + r0];
                float s1 = h / g_rs[b * NN + r0 + 8];
#pragma unroll
                for (int nt = 0; nt < 4; nt++) {
                    int col = colBase + wn * 32 + nt * 8 + 2 * q;
                    float2 b0 = *(const float2*)(base + (long)r0 * DD + col);
                    float2 b1 = *(const float2*)(base + (long)(r0 + 8) * DD + col);
                    *(float2*)(C + (long)r0 * DD + col) =
                        make_float2(b0.x + s0 * acc[mt][nt][0], b0.y + s0 * acc[mt][nt][1]);
                    *(float2*)(C + (long)(r0 + 8) * DD + col) =
                        make_float2(b1.x + s1 * acc[mt][nt][2], b1.y + s1 * acc[mt][nt][3]);
                }
            }
        }
    } else {
        const __nv_bfloat16* A = g_bf + O_ET  + (long)b * MM * NN;
        const __nv_bfloat16* B = g_bf + O_VST + (long)b * DD * NN;
        gemm_bf16(A, B, NN, NN, NN, rowBase, colBase, dsm, acc);
        if (group == 0) {
            const float* base = txt + (long)b * MM * DD;
            float* C = outt + (long)b * MM * DD;
#pragma unroll
            for (int mt = 0; mt < 2; mt++) {
                int r0 = rowBase + wm * 32 + mt * 16 + g;
#pragma unroll
                for (int nt = 0; nt < 4; nt++) {
                    int col = colBase + wn * 32 + nt * 8 + 2 * q;
                    float2 b0 = *(const float2*)(base + (long)r0 * DD + col);
                    float2 b1 = *(const float2*)(base + (long)(r0 + 8) * DD + col);
                    *(float2*)(C + (long)r0 * DD + col) =
                        make_float2(b0.x + h * acc[mt][nt][0], b0.y + h * acc[mt][nt][1]);
                    *(float2*)(C + (long)(r0 + 8) * DD + col) =
                        make_float2(b1.x + h * acc[mt][nt][2], b1.y + h * acc[mt][nt][3]);
                }
            }
        }
    }
}

// ---------------------------------------------------------------------------
extern "C" void kernel_launch(void* const* d_in, const int* in_sizes, int n_in,
                              void* d_out, int out_size)
{
    (void)in_sizes; (void)n_in; (void)out_size;

    const float* vision = (const float*)d_in[0];
    const float* text   = (const float*)d_in[1];
    const float* Wv     = (const float*)d_in[2];
    const float* bv     = (const float*)d_in[3];
    const float* Wt     = (const float*)d_in[4];
    const float* bt     = (const float*)d_in[5];
    const float* hp     = (const float*)d_in[6];

    float* outv = (float*)d_out;
    float* outt = outv + (size_t)BB * NN * DD;

    cudaFuncSetAttribute(proj_k,  cudaFuncAttributeMaxDynamicSharedMemorySize, DSMEM_BYTES);
    cudaFuncSetAttribute(score_k, cudaFuncAttributeMaxDynamicSharedMemorySize, DSMEM_BYTES);
    cudaFuncSetAttribute(out_k,   cudaFuncAttributeMaxDynamicSharedMemorySize, DSMEM_BYTES);

    // 0) bf16 copies + text^T + rowsum zero
    prep_k<<<448, 256>>>(vision, text, Wv, Wt);
    // 1) Projections + quat features (bf16)
    proj_k<<<dim3(DD / 64, RTOT / 64, 2), 512, DSMEM_BYTES>>>(bv, bt);
    // 2) Score GEMM + exp + E/E^T + rowsums
    score_k<<<dim3(MM / 64, NN / 64, BB), 512, DSMEM_BYTES>>>();
    // 3) v'^T = (vision/rowsum)^T bf16 (512 CTAs — latency hiding)
    vscale_k<<<512, 128>>>(vision);
    // 4) Both outputs in one launch
    out_k<<<dim3(DD / 64, NN / 64, 4), 512, DSMEM_BYTES>>>(
        vision, text, hp, outv, outt);
}